// round 15
// baseline (speedup 1.0000x reference)
#include <cuda_runtime.h>
#include <math.h>

#define S_LEN  4096
#define DMODEL 1024
#define DHEAD  64
#define NBATCH 2
#define NROWS  (NBATCH * S_LEN)   // 8192
#define NSPLIT 4
#define KSPLIT (S_LEN / NSPLIT)   // 1024 keys per split

typedef unsigned long long u64;

// scratch: projected q,k,v + split-K partial results
__device__ float g_q[NROWS * DHEAD];
__device__ float g_k[NROWS * DHEAD];
__device__ float g_v[NROWS * DHEAD];
__device__ float g_op[NSPLIT * NROWS * DHEAD];   // unnormalized partial O
__device__ float g_m[NSPLIT * NROWS];            // running max per row
__device__ float g_l[NSPLIT * NROWS];            // running sum per row

// ---- packed f32x2 helpers (sm_103a FFMA2 path) -----------------------------
__device__ __forceinline__ u64 dup2(float x) {
    u64 r; asm("mov.b64 %0, {%1, %1};" : "=l"(r) : "f"(x)); return r;
}
__device__ __forceinline__ void fma2(u64 &d, u64 a, u64 b) {
    asm("fma.rn.f32x2 %0, %1, %2, %0;" : "+l"(d) : "l"(a), "l"(b));
}
__device__ __forceinline__ u64 mul2(u64 a, u64 b) {
    u64 r; asm("mul.rn.f32x2 %0, %1, %2;" : "=l"(r) : "l"(a), "l"(b)); return r;
}
__device__ __forceinline__ u64 add2(u64 a, u64 b) {
    u64 r; asm("add.rn.f32x2 %0, %1, %2;" : "=l"(r) : "l"(a), "l"(b)); return r;
}
union F4U { float4 f; u64 u[2]; float s[4]; };
// load 8 consecutive floats as 4 packed pairs (two LDS.128)
__device__ __forceinline__ void ld8(const float* p, u64 b[4]) {
    F4U a, c; a.f = *(const float4*)p; c.f = *(const float4*)(p + 4);
    b[0] = a.u[0]; b[1] = a.u[1]; b[2] = c.u[0]; b[3] = c.u[1];
}

// ---------------------------------------------------------------------------
// Projection: C[row][c] = sum_m A[row][m] * W[c][m] + b[c]
// 64x64 tile per CTA, 64 threads, 8x8 microtile, FFMA2 inner loop.
// ---------------------------------------------------------------------------
__global__ __launch_bounds__(64) void proj_kernel(
    const float* __restrict__ Qin, const float* __restrict__ Kin,
    const float* __restrict__ Vin,
    const float* __restrict__ Wq, const float* __restrict__ bq,
    const float* __restrict__ Wk, const float* __restrict__ bk,
    const float* __restrict__ Wv, const float* __restrict__ bv)
{
    const float* A; const float* W; const float* bias; float* C;
    int which = blockIdx.y;
    if (which == 0)      { A = Qin; W = Wq; bias = bq; C = g_q; }
    else if (which == 1) { A = Kin; W = Wk; bias = bk; C = g_k; }
    else                 { A = Vin; W = Wv; bias = bv; C = g_v; }

    __shared__ float As[16][64];   // As[m][row]
    __shared__ float Ws[16][64];   // Ws[m][col]

    const int tid = threadIdx.x;
    const int tx = tid & 7, ty = tid >> 3;
    const int row0 = blockIdx.x * 64;

    u64 acc[8][4];
    #pragma unroll
    for (int i = 0; i < 8; i++)
        #pragma unroll
        for (int j = 0; j < 4; j++) acc[i][j] = 0ULL;

    const float* Arow = A + (size_t)(row0 + tid) * DMODEL;
    const float* Wrow = W + (size_t)tid * DMODEL;

    for (int k0 = 0; k0 < DMODEL; k0 += 16) {
        __syncthreads();
        #pragma unroll
        for (int f = 0; f < 4; f++) {
            float4 av = *(const float4*)(Arow + k0 + 4*f);
            float4 wv = *(const float4*)(Wrow + k0 + 4*f);
            As[4*f+0][tid] = av.x; As[4*f+1][tid] = av.y;
            As[4*f+2][tid] = av.z; As[4*f+3][tid] = av.w;
            Ws[4*f+0][tid] = wv.x; Ws[4*f+1][tid] = wv.y;
            Ws[4*f+2][tid] = wv.z; Ws[4*f+3][tid] = wv.w;
        }
        __syncthreads();

        #pragma unroll
        for (int m = 0; m < 16; m++) {
            F4U a0, a1;
            a0.f = *(const float4*)&As[m][ty*8];
            a1.f = *(const float4*)&As[m][ty*8+4];
            u64 a2[8] = { dup2(a0.s[0]), dup2(a0.s[1]), dup2(a0.s[2]), dup2(a0.s[3]),
                          dup2(a1.s[0]), dup2(a1.s[1]), dup2(a1.s[2]), dup2(a1.s[3]) };
            u64 b2[4]; ld8(&Ws[m][tx*8], b2);
            #pragma unroll
            for (int i = 0; i < 8; i++)
                #pragma unroll
                for (int j = 0; j < 4; j++)
                    fma2(acc[i][j], a2[i], b2[j]);
        }
    }

    u64 bb[4]; ld8(&bias[tx*8], bb);
    #pragma unroll
    for (int i = 0; i < 8; i++) {
        float* dst = C + (size_t)(row0 + ty*8 + i) * DHEAD + tx*8;
        #pragma unroll
        for (int j = 0; j < 4; j++)
            *(u64*)(dst + 2*j) = add2(acc[i][j], bb[j]);
    }
}

// ---------------------------------------------------------------------------
// Split-K flash attention partial: 64 queries x 1024 keys (one split) per CTA.
// 64 threads, 8x8 microtiles, FFMA2 both GEMMs. kt buffer reused for P^T with
// xor swizzle (q ^ (k & 56)) to kill write bank conflicts.
// ---------------------------------------------------------------------------
__global__ __launch_bounds__(64) void attn_partial(const int* __restrict__ mask)
{
    __shared__ float qt[64][64];   // qt[d][q], pre-scaled by 1/8
    __shared__ float kt[64][64];   // kt[d][k], reused as swizzled pt[k][q]
    __shared__ float vs[64][64];   // vs[k][v]

    const int tid = threadIdx.x;
    const int tx = tid & 7, ty = tid >> 3;
    const int b     = blockIdx.y & 1;
    const int split = blockIdx.y >> 1;
    const int q0     = blockIdx.x * 64;
    const int kstart = split * KSPLIT;

    // q tile, transposed + pre-scaled
    {
        const float* src = g_q + (size_t)(b * S_LEN + q0 + tid) * DHEAD;
        #pragma unroll
        for (int f = 0; f < 16; f++) {
            float4 v = *(const float4*)(src + 4*f);
            qt[4*f+0][tid] = v.x * 0.125f;
            qt[4*f+1][tid] = v.y * 0.125f;
            qt[4*f+2][tid] = v.z * 0.125f;
            qt[4*f+3][tid] = v.w * 0.125f;
        }
    }

    float m_run[8], l_run[8];
    u64 o2[8][4];
    #pragma unroll
    for (int i = 0; i < 8; i++) {
        m_run[i] = -INFINITY; l_run[i] = 0.f;
        #pragma unroll
        for (int j = 0; j < 4; j++) o2[i][j] = 0ULL;
    }

    const int* mb = mask + ((size_t)(b * S_LEN + q0 + ty*8)) * S_LEN + tx*8;

    for (int t = 0; t < KSPLIT / 64; t++) {
        const int kk0 = kstart + t * 64;
        __syncthreads();   // prev iter pt/vs readers done
        {
            const float* ks = g_k + (size_t)(b * S_LEN + kk0 + tid) * DHEAD;
            const float* vsrc = g_v + (size_t)(b * S_LEN + kk0 + tid) * DHEAD;
            #pragma unroll
            for (int f = 0; f < 16; f++) {
                float4 kv = *(const float4*)(ks + 4*f);
                kt[4*f+0][tid] = kv.x; kt[4*f+1][tid] = kv.y;
                kt[4*f+2][tid] = kv.z; kt[4*f+3][tid] = kv.w;
                *(float4*)&vs[tid][4*f] = *(const float4*)(vsrc + 4*f);
            }
        }
        __syncthreads();

        // ---- S = (q/8) . k^T, 8x8 per thread ----
        u64 s2[8][4];
        #pragma unroll
        for (int i = 0; i < 8; i++)
            #pragma unroll
            for (int j = 0; j < 4; j++) s2[i][j] = 0ULL;

        #pragma unroll 8
        for (int d = 0; d < 64; d++) {
            F4U a0, a1;
            a0.f = *(const float4*)&qt[d][ty*8];
            a1.f = *(const float4*)&qt[d][ty*8+4];
            u64 a2[8] = { dup2(a0.s[0]), dup2(a0.s[1]), dup2(a0.s[2]), dup2(a0.s[3]),
                          dup2(a1.s[0]), dup2(a1.s[1]), dup2(a1.s[2]), dup2(a1.s[3]) };
            u64 b2[4]; ld8(&kt[d][tx*8], b2);
            #pragma unroll
            for (int i = 0; i < 8; i++)
                #pragma unroll
                for (int j = 0; j < 4; j++)
                    fma2(s2[i][j], a2[i], b2[j]);
        }

        // ---- mask + online softmax (p packed back into s2) ----
        #pragma unroll
        for (int i = 0; i < 8; i++) {
            F4U u0, u1;
            u0.u[0] = s2[i][0]; u0.u[1] = s2[i][1];
            u1.u[0] = s2[i][2]; u1.u[1] = s2[i][3];
            int4 mm0 = *(const int4*)(mb + (size_t)i * S_LEN + kk0);
            int4 mm1 = *(const int4*)(mb + (size_t)i * S_LEN + kk0 + 4);
            float lg[8];
            lg[0] = mm0.x ? u0.s[0] : -1e9f;
            lg[1] = mm0.y ? u0.s[1] : -1e9f;
            lg[2] = mm0.z ? u0.s[2] : -1e9f;
            lg[3] = mm0.w ? u0.s[3] : -1e9f;
            lg[4] = mm1.x ? u1.s[0] : -1e9f;
            lg[5] = mm1.y ? u1.s[1] : -1e9f;
            lg[6] = mm1.z ? u1.s[2] : -1e9f;
            lg[7] = mm1.w ? u1.s[3] : -1e9f;
            float mx = lg[0];
            #pragma unroll
            for (int j = 1; j < 8; j++) mx = fmaxf(mx, lg[j]);
            #pragma unroll
            for (int off = 1; off < 8; off <<= 1)
                mx = fmaxf(mx, __shfl_xor_sync(0xffffffffu, mx, off));
            float nm = fmaxf(m_run[i], mx);
            float ef = __expf(m_run[i] - nm);   // exp(-inf)=0 first tile
            m_run[i] = nm;
            float lsum = 0.f;
            float p[8];
            #pragma unroll
            for (int j = 0; j < 8; j++) { p[j] = __expf(lg[j] - nm); lsum += p[j]; }
            l_run[i] = l_run[i] * ef + lsum;
            u64 e2 = dup2(ef);
            #pragma unroll
            for (int j = 0; j < 4; j++) o2[i][j] = mul2(o2[i][j], e2);
            u0.s[0]=p[0]; u0.s[1]=p[1]; u0.s[2]=p[2]; u0.s[3]=p[3];
            u1.s[0]=p[4]; u1.s[1]=p[5]; u1.s[2]=p[6]; u1.s[3]=p[7];
            s2[i][0]=u0.u[0]; s2[i][1]=u0.u[1]; s2[i][2]=u1.u[0]; s2[i][3]=u1.u[1];
        }

        __syncthreads();   // all kt reads done
        // write p^T into kt with xor swizzle: pt[k][q ^ (k & 56)]
        #pragma unroll
        for (int i = 0; i < 8; i++) {
            F4U u0, u1;
            u0.u[0] = s2[i][0]; u0.u[1] = s2[i][1];
            u1.u[0] = s2[i][2]; u1.u[1] = s2[i][3];
            #pragma unroll
            for (int j = 0; j < 8; j++) {
                int k = tx*8 + j;
                float pv = (j < 4) ? u0.s[j] : u1.s[j-4];
                kt[k][(ty*8 + i) ^ (k & 56)] = pv;
            }
        }
        __syncthreads();

        // ---- O += P^T-reads * V ----
        #pragma unroll 8
        for (int k = 0; k < 64; k++) {
            const int qc = (ty*8) ^ (k & 56);
            F4U a0, a1;
            a0.f = *(const float4*)&kt[k][qc];
            a1.f = *(const float4*)&kt[k][qc+4];
            u64 a2[8] = { dup2(a0.s[0]), dup2(a0.s[1]), dup2(a0.s[2]), dup2(a0.s[3]),
                          dup2(a1.s[0]), dup2(a1.s[1]), dup2(a1.s[2]), dup2(a1.s[3]) };
            u64 b2[4]; ld8(&vs[k][tx*8], b2);
            #pragma unroll
            for (int i = 0; i < 8; i++)
                #pragma unroll
                for (int j = 0; j < 4; j++)
                    fma2(o2[i][j], a2[i], b2[j]);
        }
    }

    // l_run is a per-lane partial (8 keys each) — reduce across the 8-lane
    // tx group before writing the split's row sum.  (R5 bug fix)
    #pragma unroll
    for (int i = 0; i < 8; i++) {
        float l = l_run[i];
        #pragma unroll
        for (int off = 1; off < 8; off <<= 1)
            l += __shfl_xor_sync(0xffffffffu, l, off);
        l_run[i] = l;
    }

    // write partial results
    const size_t rbase = (size_t)split * NROWS + b * S_LEN + q0;
    #pragma unroll
    for (int i = 0; i < 8; i++) {
        size_t row = rbase + ty*8 + i;
        float* dst = g_op + row * DHEAD + tx*8;
        #pragma unroll
        for (int j = 0; j < 4; j++) *(u64*)(dst + 2*j) = o2[i][j];
        if (tx == 0) { g_m[row] = m_run[i]; g_l[row] = l_run[i]; }
    }
}

// ---------------------------------------------------------------------------
// Combine the NSPLIT partials: y = sum_s w_s*o_s / sum_s w_s*l_s, w_s=e^{m_s-M}
// One thread per output float4.
// ---------------------------------------------------------------------------
__global__ __launch_bounds__(256) void combine_kernel(float* __restrict__ out)
{
    int idx = blockIdx.x * 256 + threadIdx.x;   // NROWS*16 total
    int row = idx >> 4;
    int c   = (idx & 15) * 4;

    float m[NSPLIT], l[NSPLIT];
    float M = -INFINITY;
    #pragma unroll
    for (int s = 0; s < NSPLIT; s++) {
        m[s] = g_m[s * NROWS + row];
        l[s] = g_l[s * NROWS + row];
        M = fmaxf(M, m[s]);
    }
    float L = 0.f;
    float4 acc = make_float4(0.f, 0.f, 0.f, 0.f);
    #pragma unroll
    for (int s = 0; s < NSPLIT; s++) {
        float w = __expf(m[s] - M);
        L += w * l[s];
        float4 o = *(const float4*)&g_op[((size_t)s * NROWS + row) * DHEAD + c];
        acc.x += w * o.x; acc.y += w * o.y; acc.z += w * o.z; acc.w += w * o.w;
    }
    float inv = 1.f / L;
    float4 r = make_float4(acc.x*inv, acc.y*inv, acc.z*inv, acc.w*inv);
    *(float4*)&out[(size_t)row * DHEAD + c] = r;
}

extern "C" void kernel_launch(void* const* d_in, const int* in_sizes, int n_in,
                              void* d_out, int out_size)
{
    const float* Q    = (const float*)d_in[0];
    const float* K    = (const float*)d_in[1];
    const float* V    = (const float*)d_in[2];
    const int*   mask = (const int*)  d_in[3];
    const float* Wq   = (const float*)d_in[4];
    const float* bq   = (const float*)d_in[5];
    const float* Wk   = (const float*)d_in[6];
    const float* bk   = (const float*)d_in[7];
    const float* Wv   = (const float*)d_in[8];
    const float* bv   = (const float*)d_in[9];
    float* out = (float*)d_out;

    dim3 pgrid(NROWS / 64, 3);
    proj_kernel<<<pgrid, 64>>>(Q, K, V, Wq, bq, Wk, bk, Wv, bv);

    dim3 agrid(S_LEN / 64, NBATCH * NSPLIT);
    attn_partial<<<agrid, 64>>>(mask);

    combine_kernel<<<(NROWS * 16) / 256, 256>>>(out);
}